// round 9
// baseline (speedup 1.0000x reference)
#include <cuda_runtime.h>
#include <cstdint>

#define N_NODES 100000
#define N_EDGES 1600000
#define C 32

// Scratch (device globals; zero-initialized at module load).
// g_degi is consumed and re-zeroed by k_gemm each call -> replay-safe.
__device__ int    g_degi[N_NODES];
__device__ float  g_dinv[N_NODES];
__device__ float4 g_hs[N_NODES * (C / 4)];   // hs[i] = (x[i] @ W^T) * dinv[i]

// ---------------------------------------------------------------------------
// K1: in-degree histogram over targets, 1 edge/thread (proven 12.7us shape).
__global__ void k_count(const int* __restrict__ col) {
    int e = blockIdx.x * blockDim.x + threadIdx.x;
    if (e < N_EDGES) atomicAdd(&g_degi[__ldg(col + e)], 1);
}

// K2: dinv = rsqrt(deg+1); hs = (x @ W^T) * dinv; out = hs (self-loop init).
//     Re-zeroes g_degi for the next replay. Block = 8 nodes x 32 channels.
__global__ void k_gemm(const float* __restrict__ x,
                       const float* __restrict__ W,
                       float* __restrict__ out) {
    __shared__ float Wsh[C][C + 1];   // Wsh[k][co] = W[co*C + k]
    int tid = threadIdx.x;
    #pragma unroll
    for (int i = tid; i < C * C; i += 256) {
        Wsh[i % C][i / C] = W[i];
    }
    __syncthreads();

    int n  = blockIdx.x * 8 + (tid >> 5);
    int co = tid & 31;
    if (n >= N_NODES) return;

    int deg = g_degi[n];
    if (co == 0) g_degi[n] = 0;                    // reset for next replay
    float dinv = rsqrtf((float)(deg + 1));         // +1 = self loop
    if (co == 0) g_dinv[n] = dinv;

    const float* xr = x + n * C;
    float acc = 0.0f;
    #pragma unroll
    for (int k = 0; k < C; k++) acc += __ldg(xr + k) * Wsh[k][co];

    float hs = acc * dinv;
    reinterpret_cast<float*>(g_hs)[n * C + co] = hs;
    out[n * C + co] = hs;   // self-loop accumulator init
}

// K3: edge scatter — out[col] += hs[row]. EXACT R1 shape (measured 50.5us,
//     at the REDG spread-lane floor): 1 edge per 8-thread group, one float4
//     load + one RED.v4 per thread, nothing else on the LSU path.
__global__ void k_scatter(const int* __restrict__ rowv,
                          const int* __restrict__ colv,
                          float* __restrict__ out) {
    int t = blockIdx.x * blockDim.x + threadIdx.x;
    int e = t >> 3;
    int g = t & 7;
    if (e >= N_EDGES) return;

    int r = __ldg(rowv + e);
    int c = __ldg(colv + e);
    float4 v = g_hs[r * 8 + g];
    float* dst = out + (size_t)c * C + g * 4;
    asm volatile("red.global.add.v4.f32 [%0], {%1, %2, %3, %4};"
                 :: "l"(dst), "f"(v.x), "f"(v.y), "f"(v.z), "f"(v.w)
                 : "memory");
}

// K4: out = out * dinv[node] + b[channel], float4 per thread.
__global__ void k_final(float4* __restrict__ out, const float* __restrict__ b) {
    int i = blockIdx.x * blockDim.x + threadIdx.x;
    if (i < N_NODES * 8) {
        int n = i >> 3;
        int g = i & 7;
        float d = g_dinv[n];
        float4 v = out[i];
        float4 bb = *reinterpret_cast<const float4*>(b + g * 4);
        v.x = fmaf(v.x, d, bb.x);
        v.y = fmaf(v.y, d, bb.y);
        v.z = fmaf(v.z, d, bb.z);
        v.w = fmaf(v.w, d, bb.w);
        out[i] = v;
    }
}

// ---------------------------------------------------------------------------
extern "C" void kernel_launch(void* const* d_in, const int* in_sizes, int n_in,
                              void* d_out, int out_size) {
    const float* x  = (const float*)d_in[0];
    const int*   ei = (const int*)d_in[1];    // [2, E]: row then col
    const float* W  = (const float*)d_in[2];
    const float* b  = (const float*)d_in[3];
    float* out = (float*)d_out;

    const int* rowv = ei;
    const int* colv = ei + N_EDGES;

    k_count<<<(N_EDGES + 255) / 256, 256>>>(colv);
    k_gemm<<<(N_NODES + 7) / 8, 256>>>(x, W, out);
    k_scatter<<<(N_EDGES * 8 + 255) / 256, 256>>>(rowv, colv, out);
    k_final<<<(N_NODES * 8 + 511) / 512, 512>>>((float4*)out, b);
}